// round 5
// baseline (speedup 1.0000x reference)
#include <cuda_runtime.h>
#include <cstdint>

// Problem constants (fixed by the dataset)
#define NMAX      50000
#define IN_FEATS  256
#define NHEADS    4
#define OUTF      64
#define HF        (NHEADS * OUTF)   // 256 = per-node projected width
#define EMAX      (NMAX * 16)       // 800000 edges
#define NEG_SLOPE 0.2f
#define MAXDEG    32                // dataset uses fixed deg=16; headroom

// ---------------------------------------------------------------------------
// Scratch (no cudaMalloc allowed)
// ---------------------------------------------------------------------------
__device__ float g_h[(size_t)NMAX * HF];        // 51.2 MB projected features
__device__ float g_attn_row[(size_t)NMAX * NHEADS];
__device__ float g_attn_col[(size_t)NMAX * NHEADS];
__device__ int   g_row_ptr[NMAX + 1];           // int32-normalized CSR
__device__ int   g_col_ind[EMAX];

// ---------------------------------------------------------------------------
// Kernel 0: normalize index arrays to int32.
// JAX without x64 silently makes "int64" arrays int32 — detect on device:
// element 1 of row_ptr is DEG(=16). Read as int32 words:
//   int32 layout -> words[1] == 16 ; int64 layout -> words[1] == 0 (high word).
// ---------------------------------------------------------------------------
__global__ void convert_idx_kernel(const void* __restrict__ row_ptr_raw,
                                   const void* __restrict__ col_ind_raw,
                                   int n_plus1, int e)
{
    const int i = blockIdx.x * blockDim.x + threadIdx.x;
    const int* rp32 = (const int*)row_ptr_raw;
    const bool is64 = (rp32[1] == 0);

    if (i < n_plus1) {
        g_row_ptr[i] = is64 ? (int)((const long long*)row_ptr_raw)[i]
                            : rp32[i];
    }
    if (i < e) {
        g_col_ind[i] = is64 ? (int)((const long long*)col_ind_raw)[i]
                            : ((const int*)col_ind_raw)[i];
    }
}

// ---------------------------------------------------------------------------
// Kernel 1: SGEMM  h[M,256] = feat[M,256] @ W[256,256]
// Classic 128x128 tile, BK=8, 256 threads, 8x8 per-thread register tile.
// ---------------------------------------------------------------------------
#define BM 128
#define BN 128
#define BK 8
#define TM 8
#define TN 8

__global__ __launch_bounds__(256) void sgemm_kernel(
    const float* __restrict__ A,   // [M, 256]
    const float* __restrict__ B,   // [256, 256]
    int M)
{
    const int K = IN_FEATS;
    const int N = HF;

    __shared__ float As[BK][BM];
    __shared__ float Bs[BK][BN];

    const int block_m = blockIdx.y * BM;
    const int block_n = blockIdx.x * BN;
    const int tid = threadIdx.x;

    const int tx = tid & 15;   // N direction (16 threads)
    const int ty = tid >> 4;   // M direction (16 threads)

    // A-tile load map: 128 rows x 8 cols = 256 float4; one float4 per thread
    const int a_row = tid >> 1;
    const int a_col = (tid & 1) * 4;
    // B-tile load map: 8 rows x 128 cols = 256 float4
    const int b_row = tid >> 5;
    const int b_col = (tid & 31) * 4;

    float acc[TM][TN];
#pragma unroll
    for (int i = 0; i < TM; i++)
#pragma unroll
        for (int j = 0; j < TN; j++) acc[i][j] = 0.0f;

    for (int k0 = 0; k0 < K; k0 += BK) {
        // Load A tile (guarded on M), store transposed As[k][m]
        float4 av = make_float4(0.f, 0.f, 0.f, 0.f);
        const int gm = block_m + a_row;
        if (gm < M)
            av = *reinterpret_cast<const float4*>(A + (size_t)gm * K + k0 + a_col);
        As[a_col + 0][a_row] = av.x;
        As[a_col + 1][a_row] = av.y;
        As[a_col + 2][a_row] = av.z;
        As[a_col + 3][a_row] = av.w;

        // Load B tile (K,N both multiples of tile — unguarded)
        const float4 bv = *reinterpret_cast<const float4*>(
            B + (size_t)(k0 + b_row) * N + block_n + b_col);
        *reinterpret_cast<float4*>(&Bs[b_row][b_col]) = bv;

        __syncthreads();

#pragma unroll
        for (int k = 0; k < BK; k++) {
            float ar[TM], br[TN];
#pragma unroll
            for (int i = 0; i < TM; i++) ar[i] = As[k][ty * TM + i];
#pragma unroll
            for (int j = 0; j < TN; j++) br[j] = Bs[k][tx * TN + j];
#pragma unroll
            for (int i = 0; i < TM; i++)
#pragma unroll
                for (int j = 0; j < TN; j++)
                    acc[i][j] = fmaf(ar[i], br[j], acc[i][j]);
        }
        __syncthreads();
    }

    // Store C tile
#pragma unroll
    for (int i = 0; i < TM; i++) {
        const int gm = block_m + ty * TM + i;
        if (gm < M) {
            float* crow = g_h + (size_t)gm * N + block_n + tx * TN;
#pragma unroll
            for (int j = 0; j < TN; j += 4) {
                float4 v = make_float4(acc[i][j], acc[i][j + 1],
                                       acc[i][j + 2], acc[i][j + 3]);
                *reinterpret_cast<float4*>(crow + j) = v;
            }
        }
    }
}

// ---------------------------------------------------------------------------
// Kernel 2: per-node attention scores
//   attn_row[n,h] = sum_f attn_l[h,f] * h[n,h,f]
//   attn_col[n,h] = sum_f attn_r[h,f] * h[n,h,f]
// One CTA (256 threads) per node; single pass over h.
// ---------------------------------------------------------------------------
__global__ __launch_bounds__(256) void attn_score_kernel(
    const float* __restrict__ attn_l,   // [256] = [H,F] flattened
    const float* __restrict__ attn_r)
{
    const int node = blockIdx.x;
    const int tid = threadIdx.x;

    const float v = g_h[(size_t)node * HF + tid];
    float pl = v * attn_l[tid];
    float pr = v * attn_r[tid];

    // warp reduce (32 lanes)
#pragma unroll
    for (int off = 16; off > 0; off >>= 1) {
        pl += __shfl_xor_sync(0xFFFFFFFFu, pl, off);
        pr += __shfl_xor_sync(0xFFFFFFFFu, pr, off);
    }

    __shared__ float sl[8], sr[8];
    const int wid = tid >> 5;
    if ((tid & 31) == 0) { sl[wid] = pl; sr[wid] = pr; }
    __syncthreads();

    // head h spans warps 2h and 2h+1 (64 lanes per head)
    if (tid < NHEADS) {
        g_attn_row[(size_t)node * NHEADS + tid] = sl[2 * tid] + sl[2 * tid + 1];
        g_attn_col[(size_t)node * NHEADS + tid] = sr[2 * tid] + sr[2 * tid + 1];
    }
}

// ---------------------------------------------------------------------------
// Kernel 3: per-destination softmax + weighted gather-aggregate.
// CSR rows are destinations -> edges of a dst are contiguous, no atomics.
// One CTA (256 threads) per destination node.
// ---------------------------------------------------------------------------
__global__ __launch_bounds__(256) void gat_agg_kernel(float* __restrict__ out)
{
    const int dst = blockIdx.x;
    const int tid = threadIdx.x;

    const int e0 = g_row_ptr[dst];
    int deg = g_row_ptr[dst + 1] - e0;
    if (deg > MAXDEG) deg = MAXDEG;   // safety clamp (dataset: deg == 16)

    __shared__ int   s_src[MAXDEG];
    __shared__ float s_alpha[MAXDEG * NHEADS];

    if (tid < deg) s_src[tid] = g_col_ind[e0 + tid];
    __syncthreads();

    // raw scores + leaky relu: one thread per (edge, head)
    if (tid < deg * NHEADS) {
        const int e = tid >> 2;
        const int h = tid & 3;
        float s = g_attn_row[(size_t)dst * NHEADS + h] +
                  g_attn_col[(size_t)s_src[e] * NHEADS + h];
        s = (s >= 0.f) ? s : NEG_SLOPE * s;
        s_alpha[e * NHEADS + h] = s;
    }
    __syncthreads();

    // softmax over the deg edges, per head (deg is tiny: serial per head)
    if (tid < NHEADS) {
        float m = -1e30f;
        for (int e = 0; e < deg; e++)
            m = fmaxf(m, s_alpha[e * NHEADS + tid]);
        float sum = 0.f;
        for (int e = 0; e < deg; e++) {
            float ex = __expf(s_alpha[e * NHEADS + tid] - m);
            s_alpha[e * NHEADS + tid] = ex;
            sum += ex;
        }
        const float inv = 1.0f / sum;
        for (int e = 0; e < deg; e++)
            s_alpha[e * NHEADS + tid] *= inv;
    }
    __syncthreads();

    // aggregate: thread tid owns output feature (h = tid/64, f = tid%64)
    const int h = tid >> 6;
    float acc = 0.f;
#pragma unroll 4
    for (int e = 0; e < deg; e++) {
        acc = fmaf(s_alpha[e * NHEADS + h],
                   __ldg(&g_h[(size_t)s_src[e] * HF + tid]), acc);
    }
    out[(size_t)dst * HF + tid] = acc;
}

// ---------------------------------------------------------------------------
// Launch
// Inputs (metadata order): row_ptr(N+1), col_ind(E), col_ptr(N+1), row_ind(E),
// feat(f32,N*256), W(f32,256*256), attn_l(f32,256), attn_r(f32,256)
// Output: f32 [N, 4, 64]
// ---------------------------------------------------------------------------
extern "C" void kernel_launch(void* const* d_in, const int* in_sizes, int n_in,
                              void* d_out, int out_size)
{
    const void*  row_ptr_raw = d_in[0];
    const void*  col_ind_raw = d_in[1];
    const float* feat   = (const float*)d_in[4];
    const float* W      = (const float*)d_in[5];
    const float* attn_l = (const float*)d_in[6];
    const float* attn_r = (const float*)d_in[7];
    float* out = (float*)d_out;

    const int n_plus1 = in_sizes[0];      // N + 1
    const int n = n_plus1 - 1;            // 50000
    int e = in_sizes[1];                  // 800000
    if (e > EMAX) e = EMAX;

    // 0) normalize indices to int32 (handles int32-or-int64 input layout)
    {
        const int total = (e > n_plus1) ? e : n_plus1;
        convert_idx_kernel<<<(total + 255) / 256, 256>>>(
            row_ptr_raw, col_ind_raw, n_plus1, e);
    }

    // 1) h = feat @ W
    dim3 ggrid(HF / BN, (n + BM - 1) / BM);
    sgemm_kernel<<<ggrid, 256>>>(feat, W, n);

    // 2) attn_row / attn_col
    attn_score_kernel<<<n, 256>>>(attn_l, attn_r);

    // 3) softmax + aggregate
    gat_agg_kernel<<<n, 256>>>(out);
}

// round 6
// speedup vs baseline: 2.0825x; 2.0825x over previous
#include <cuda_runtime.h>
#include <cstdint>

// Problem constants (fixed by the dataset)
#define NMAX      50000
#define IN_FEATS  256
#define NHEADS    4
#define OUTF      64
#define HF        (NHEADS * OUTF)   // 256 = per-node projected width
#define EMAX      (NMAX * 16)       // 800000 edges
#define NEG_SLOPE 0.2f
#define MAXDEG    16                // dataset uses fixed deg=16

// ---------------------------------------------------------------------------
// Scratch (no cudaMalloc allowed)
// ---------------------------------------------------------------------------
__device__ float g_h[(size_t)NMAX * HF];        // 51.2 MB projected features
__device__ float g_attn_row[(size_t)NMAX * NHEADS];
__device__ float g_attn_col[(size_t)NMAX * NHEADS];
__device__ int   g_row_ptr[NMAX + 1];           // int32-normalized CSR
__device__ int   g_col_ind[EMAX];

// ---------------------------------------------------------------------------
// Kernel 0: normalize index arrays to int32 (input may be int32 or int64).
// row_ptr[1] == DEG(16): int32 layout -> words[1]==16 ; int64 -> words[1]==0.
// ---------------------------------------------------------------------------
__global__ void convert_idx_kernel(const void* __restrict__ row_ptr_raw,
                                   const void* __restrict__ col_ind_raw,
                                   int n_plus1, int e)
{
    const int i = blockIdx.x * blockDim.x + threadIdx.x;
    const int* rp32 = (const int*)row_ptr_raw;
    const bool is64 = (rp32[1] == 0);

    if (i < n_plus1) {
        g_row_ptr[i] = is64 ? (int)((const long long*)row_ptr_raw)[i] : rp32[i];
    }
    if (i < e) {
        g_col_ind[i] = is64 ? (int)((const long long*)col_ind_raw)[i]
                            : ((const int*)col_ind_raw)[i];
    }
}

// ---------------------------------------------------------------------------
// Kernel 1: tf32 tensor-core GEMM  h[M,256] = feat[M,256] @ W[256,256]
// CTA tile 128x128x16, 8 warps in 2(M)x4(N), warp tile 64x32,
// mma.sync.aligned.m16n8k8 tf32, fp32 accumulate. Double-buffered smem.
// SMEM padding chosen so all fragment LDS patterns are 32-bank conflict-free:
//   A stored [row][k] stride 20 floats, B stored [k][n] stride 136 floats.
// ---------------------------------------------------------------------------
#define GBM 128
#define GBN 128
#define GBK 16
#define A_STRIDE 20
#define B_STRIDE 136

__device__ __forceinline__ uint32_t f2tf32(float x) {
    uint32_t r;
    asm("cvt.rna.tf32.f32 %0, %1;" : "=r"(r) : "f"(x));
    return r;
}

__device__ __forceinline__ void mma_tf32(float* c, const uint32_t* a,
                                         const uint32_t* b) {
    asm volatile(
        "mma.sync.aligned.m16n8k8.row.col.f32.tf32.tf32.f32 "
        "{%0,%1,%2,%3}, {%4,%5,%6,%7}, {%8,%9}, {%0,%1,%2,%3};"
        : "+f"(c[0]), "+f"(c[1]), "+f"(c[2]), "+f"(c[3])
        : "r"(a[0]), "r"(a[1]), "r"(a[2]), "r"(a[3]), "r"(b[0]), "r"(b[1]));
}

__global__ __launch_bounds__(256) void gemm_tf32_kernel(
    const float* __restrict__ A,   // [M, 256]
    const float* __restrict__ B,   // [256, 256]
    int M)
{
    const int K = IN_FEATS;
    const int N = HF;

    __shared__ uint32_t As[2][GBM * A_STRIDE];  // 2 x 10240 B
    __shared__ uint32_t Bs[2][GBK * B_STRIDE];  // 2 x  8704 B

    const int tid  = threadIdx.x;
    const int lane = tid & 31;
    const int warp = tid >> 5;
    const int warp_m = warp >> 2;      // 0..1 -> 64-row strip
    const int warp_n = warp & 3;       // 0..3 -> 32-col strip

    const int block_m = blockIdx.x * GBM;
    const int block_n = blockIdx.y * GBN;

    // global->smem load maps (2 float4 per thread per tile)
    const int a_row = tid >> 1;                 // 0..127
    const int a_c0  = (tid & 1) * 8;            // float col 0 or 8
    const int b_row = tid >> 4;                 // 0..15
    const int b_c0  = (tid & 15) * 8;           // float col

    const int gid = lane >> 2;                  // 0..7
    const int tig = lane & 3;                   // 0..3

    float acc[4][4][4];
#pragma unroll
    for (int mt = 0; mt < 4; mt++)
#pragma unroll
        for (int nt = 0; nt < 4; nt++)
#pragma unroll
            for (int i = 0; i < 4; i++) acc[mt][nt][i] = 0.0f;

    float4 pa0, pa1, pb0, pb1;

    // ---- load tile 0 ----
    {
        const int gm = block_m + a_row;
        if (gm < M) {
            pa0 = *reinterpret_cast<const float4*>(A + (size_t)gm * K + a_c0);
            pa1 = *reinterpret_cast<const float4*>(A + (size_t)gm * K + a_c0 + 4);
        } else {
            pa0 = make_float4(0.f, 0.f, 0.f, 0.f); pa1 = pa0;
        }
        pb0 = *reinterpret_cast<const float4*>(B + (size_t)b_row * N + block_n + b_c0);
        pb1 = *reinterpret_cast<const float4*>(B + (size_t)b_row * N + block_n + b_c0 + 4);
    }
    {
        uint32_t* as = &As[0][a_row * A_STRIDE + a_c0];
        as[0] = f2tf32(pa0.x); as[1] = f2tf32(pa0.y);
        as[2] = f2tf32(pa0.z); as[3] = f2tf32(pa0.w);
        as[4] = f2tf32(pa1.x); as[5] = f2tf32(pa1.y);
        as[6] = f2tf32(pa1.z); as[7] = f2tf32(pa1.w);
        uint32_t* bs = &Bs[0][b_row * B_STRIDE + b_c0];
        bs[0] = f2tf32(pb0.x); bs[1] = f2tf32(pb0.y);
        bs[2] = f2tf32(pb0.z); bs[3] = f2tf32(pb0.w);
        bs[4] = f2tf32(pb1.x); bs[5] = f2tf32(pb1.y);
        bs[6] = f2tf32(pb1.z); bs[7] = f2tf32(pb1.w);
    }
    __syncthreads();

    const int NT = K / GBK;   // 16 iterations
    for (int t = 0; t < NT; t++) {
        const int cur = t & 1;

        // prefetch next tile from global
        if (t < NT - 1) {
            const int k0 = (t + 1) * GBK;
            const int gm = block_m + a_row;
            if (gm < M) {
                pa0 = *reinterpret_cast<const float4*>(A + (size_t)gm * K + k0 + a_c0);
                pa1 = *reinterpret_cast<const float4*>(A + (size_t)gm * K + k0 + a_c0 + 4);
            } else {
                pa0 = make_float4(0.f, 0.f, 0.f, 0.f); pa1 = pa0;
            }
            pb0 = *reinterpret_cast<const float4*>(B + (size_t)(k0 + b_row) * N + block_n + b_c0);
            pb1 = *reinterpret_cast<const float4*>(B + (size_t)(k0 + b_row) * N + block_n + b_c0 + 4);
        }

        // compute: 2 k-chunks of 8
#pragma unroll
        for (int kc = 0; kc < 2; kc++) {
            uint32_t af[4][4], bf[4][2];
            const int kb = kc * 8;
#pragma unroll
            for (int mt = 0; mt < 4; mt++) {
                const int r0 = warp_m * 64 + mt * 16 + gid;
                af[mt][0] = As[cur][r0 * A_STRIDE + kb + tig];
                af[mt][1] = As[cur][(r0 + 8) * A_STRIDE + kb + tig];
                af[mt][2] = As[cur][r0 * A_STRIDE + kb + tig + 4];
                af[mt][3] = As[cur][(r0 + 8) * A_STRIDE + kb + tig + 4];
            }
#pragma unroll
            for (int nt = 0; nt < 4; nt++) {
                const int cn = warp_n * 32 + nt * 8 + gid;
                bf[nt][0] = Bs[cur][(kb + tig) * B_STRIDE + cn];
                bf[nt][1] = Bs[cur][(kb + tig + 4) * B_STRIDE + cn];
            }
#pragma unroll
            for (int mt = 0; mt < 4; mt++)
#pragma unroll
                for (int nt = 0; nt < 4; nt++)
                    mma_tf32(acc[mt][nt], af[mt], bf[nt]);
        }

        // store prefetched tile to other buffer
        if (t < NT - 1) {
            const int nxt = (t + 1) & 1;
            uint32_t* as = &As[nxt][a_row * A_STRIDE + a_c0];
            as[0] = f2tf32(pa0.x); as[1] = f2tf32(pa0.y);
            as[2] = f2tf32(pa0.z); as[3] = f2tf32(pa0.w);
            as[4] = f2tf32(pa1.x); as[5] = f2tf32(pa1.y);
            as[6] = f2tf32(pa1.z); as[7] = f2tf32(pa1.w);
            uint32_t* bs = &Bs[nxt][b_row * B_STRIDE + b_c0];
            bs[0] = f2tf32(pb0.x); bs[1] = f2tf32(pb0.y);
            bs[2] = f2tf32(pb0.z); bs[3] = f2tf32(pb0.w);
            bs[4] = f2tf32(pb1.x); bs[5] = f2tf32(pb1.y);
            bs[6] = f2tf32(pb1.z); bs[7] = f2tf32(pb1.w);
            __syncthreads();
        }
    }

    // epilogue: write h
#pragma unroll
    for (int mt = 0; mt < 4; mt++) {
        const int r0 = block_m + warp_m * 64 + mt * 16 + gid;
        const int r1 = r0 + 8;
#pragma unroll
        for (int nt = 0; nt < 4; nt++) {
            const int cn = block_n + warp_n * 32 + nt * 8 + tig * 2;
            if (r0 < M) {
                float2 v = make_float2(acc[mt][nt][0], acc[mt][nt][1]);
                *reinterpret_cast<float2*>(g_h + (size_t)r0 * HF + cn) = v;
            }
            if (r1 < M) {
                float2 v = make_float2(acc[mt][nt][2], acc[mt][nt][3]);
                *reinterpret_cast<float2*>(g_h + (size_t)r1 * HF + cn) = v;
            }
        }
    }
}

// ---------------------------------------------------------------------------
// Kernel 2: per-node attention scores (single pass over h)
// ---------------------------------------------------------------------------
__global__ __launch_bounds__(256) void attn_score_kernel(
    const float* __restrict__ attn_l,   // [256] = [H,F] flattened
    const float* __restrict__ attn_r)
{
    const int node = blockIdx.x;
    const int tid = threadIdx.x;

    const float v = g_h[(size_t)node * HF + tid];
    float pl = v * attn_l[tid];
    float pr = v * attn_r[tid];

#pragma unroll
    for (int off = 16; off > 0; off >>= 1) {
        pl += __shfl_xor_sync(0xFFFFFFFFu, pl, off);
        pr += __shfl_xor_sync(0xFFFFFFFFu, pr, off);
    }

    __shared__ float sl[8], sr[8];
    const int wid = tid >> 5;
    if ((tid & 31) == 0) { sl[wid] = pl; sr[wid] = pr; }
    __syncthreads();

    if (tid < NHEADS) {
        g_attn_row[(size_t)node * NHEADS + tid] = sl[2 * tid] + sl[2 * tid + 1];
        g_attn_col[(size_t)node * NHEADS + tid] = sr[2 * tid] + sr[2 * tid + 1];
    }
}

// ---------------------------------------------------------------------------
// Kernel 3: softmax + weighted gather-aggregate.
// 4 destinations per CTA, 64 threads per destination, float4 gathers.
// ---------------------------------------------------------------------------
__global__ __launch_bounds__(256) void gat_agg_kernel(float* __restrict__ out,
                                                      int n)
{
    const int tid = threadIdx.x;
    const int group = tid >> 6;         // 0..3
    const int gt = tid & 63;            // thread within group
    const int dst = blockIdx.x * 4 + group;
    const bool valid = dst < n;

    __shared__ int   s_src[4][MAXDEG];
    __shared__ float s_alpha[4][MAXDEG * NHEADS];

    int e0 = 0, deg = 0;
    if (valid) {
        e0 = g_row_ptr[dst];
        deg = g_row_ptr[dst + 1] - e0;
        if (deg > MAXDEG) deg = MAXDEG;
    }
    if (valid && gt < deg) s_src[group][gt] = g_col_ind[e0 + gt];
    __syncthreads();

    // raw scores + leaky relu: one thread per (edge, head)
    if (valid && gt < deg * NHEADS) {
        const int e = gt >> 2;
        const int hh = gt & 3;
        float s = g_attn_row[(size_t)dst * NHEADS + hh] +
                  g_attn_col[(size_t)s_src[group][e] * NHEADS + hh];
        s_alpha[group][gt] = (s >= 0.f) ? s : NEG_SLOPE * s;
    }
    __syncthreads();

    // per-head softmax over deg edges (deg tiny)
    if (valid && gt < NHEADS) {
        float m = -1e30f;
        for (int e = 0; e < deg; e++)
            m = fmaxf(m, s_alpha[group][e * NHEADS + gt]);
        float sum = 0.f;
        for (int e = 0; e < deg; e++) {
            float ex = __expf(s_alpha[group][e * NHEADS + gt] - m);
            s_alpha[group][e * NHEADS + gt] = ex;
            sum += ex;
        }
        const float inv = 1.0f / sum;
        for (int e = 0; e < deg; e++)
            s_alpha[group][e * NHEADS + gt] *= inv;
    }
    __syncthreads();
    if (!valid) return;

    // aggregate: thread owns 4 consecutive output floats
    const int h = gt >> 4;              // head = (gt*4)/64
    const int foff = gt * 4;
    float4 acc = make_float4(0.f, 0.f, 0.f, 0.f);

    if (deg == MAXDEG) {
#pragma unroll
        for (int e = 0; e < MAXDEG; e++) {
            const float a = s_alpha[group][e * NHEADS + h];
            const float4 v = *reinterpret_cast<const float4*>(
                g_h + (size_t)s_src[group][e] * HF + foff);
            acc.x = fmaf(a, v.x, acc.x);
            acc.y = fmaf(a, v.y, acc.y);
            acc.z = fmaf(a, v.z, acc.z);
            acc.w = fmaf(a, v.w, acc.w);
        }
    } else {
        for (int e = 0; e < deg; e++) {
            const float a = s_alpha[group][e * NHEADS + h];
            const float4 v = *reinterpret_cast<const float4*>(
                g_h + (size_t)s_src[group][e] * HF + foff);
            acc.x = fmaf(a, v.x, acc.x);
            acc.y = fmaf(a, v.y, acc.y);
            acc.z = fmaf(a, v.z, acc.z);
            acc.w = fmaf(a, v.w, acc.w);
        }
    }
    *reinterpret_cast<float4*>(out + (size_t)dst * HF + foff) = acc;
}

// ---------------------------------------------------------------------------
// Launch
// Inputs (metadata order): row_ptr(N+1), col_ind(E), col_ptr(N+1), row_ind(E),
// feat(f32,N*256), W(f32,256*256), attn_l(f32,256), attn_r(f32,256)
// Output: f32 [N, 4, 64]
// ---------------------------------------------------------------------------
extern "C" void kernel_launch(void* const* d_in, const int* in_sizes, int n_in,
                              void* d_out, int out_size)
{
    const void*  row_ptr_raw = d_in[0];
    const void*  col_ind_raw = d_in[1];
    const float* feat   = (const float*)d_in[4];
    const float* W      = (const float*)d_in[5];
    const float* attn_l = (const float*)d_in[6];
    const float* attn_r = (const float*)d_in[7];
    float* out = (float*)d_out;

    const int n_plus1 = in_sizes[0];      // N + 1
    const int n = n_plus1 - 1;            // 50000
    int e = in_sizes[1];                  // 800000
    if (e > EMAX) e = EMAX;

    // 0) normalize indices to int32
    {
        const int total = (e > n_plus1) ? e : n_plus1;
        convert_idx_kernel<<<(total + 255) / 256, 256>>>(
            row_ptr_raw, col_ind_raw, n_plus1, e);
    }

    // 1) h = feat @ W  (tf32 tensor cores)
    dim3 ggrid((n + GBM - 1) / GBM, HF / GBN);
    gemm_tf32_kernel<<<ggrid, 256>>>(feat, W, n);

    // 2) attn_row / attn_col
    attn_score_kernel<<<n, 256>>>(attn_l, attn_r);

    // 3) softmax + aggregate
    gat_agg_kernel<<<(n + 3) / 4, 256>>>(out, n);
}

// round 7
// speedup vs baseline: 2.3808x; 1.1432x over previous
#include <cuda_runtime.h>
#include <cstdint>

// Problem constants (fixed by the dataset)
#define NMAX      50000
#define IN_FEATS  256
#define NHEADS    4
#define OUTF      64
#define HF        (NHEADS * OUTF)   // 256 = per-node projected width
#define EMAX      (NMAX * 16)       // 800000 edges
#define NEG_SLOPE 0.2f
#define MAXDEG    16                // dataset uses fixed deg=16

// ---------------------------------------------------------------------------
// Scratch (no cudaMalloc allowed)
// ---------------------------------------------------------------------------
__device__ float g_h[(size_t)NMAX * HF];        // 51.2 MB projected features
__device__ float g_attn_row[(size_t)NMAX * NHEADS];
__device__ float g_attn_col[(size_t)NMAX * NHEADS];
__device__ int   g_row_ptr[NMAX + 1];           // int32-normalized CSR
__device__ int   g_col_ind[EMAX];

// ---------------------------------------------------------------------------
// Kernel 0: normalize index arrays to int32 (input may be int32 or int64),
// and zero the attn partial-sum arrays (GEMM epilogue accumulates into them).
// row_ptr[1] == DEG(16): int32 layout -> words[1]==16 ; int64 -> words[1]==0.
// ---------------------------------------------------------------------------
__global__ void convert_idx_kernel(const void* __restrict__ row_ptr_raw,
                                   const void* __restrict__ col_ind_raw,
                                   int n_plus1, int e, int nh)
{
    const int i = blockIdx.x * blockDim.x + threadIdx.x;
    const int* rp32 = (const int*)row_ptr_raw;
    const bool is64 = (rp32[1] == 0);

    if (i < n_plus1) {
        g_row_ptr[i] = is64 ? (int)((const long long*)row_ptr_raw)[i] : rp32[i];
    }
    if (i < e) {
        g_col_ind[i] = is64 ? (int)((const long long*)col_ind_raw)[i]
                            : ((const int*)col_ind_raw)[i];
    }
    if (i < nh) {
        g_attn_row[i] = 0.0f;
        g_attn_col[i] = 0.0f;
    }
}

// ---------------------------------------------------------------------------
// Kernel 1: tf32 tensor-core GEMM  h[M,256] = feat[M,256] @ W[256,256]
// CTA tile 128x128x16, 8 warps in 2(M)x4(N), warp tile 64x32,
// mma.sync.aligned.m16n8k8 tf32, fp32 accumulate. Double-buffered smem.
// Fused epilogue: per-row attn_l/attn_r partial dot products -> atomicAdd
// into g_attn_row / g_attn_col (each 32-col warp strip lies in one head).
// ---------------------------------------------------------------------------
#define GBM 128
#define GBN 128
#define GBK 16
#define A_STRIDE 20
#define B_STRIDE 136

__device__ __forceinline__ uint32_t f2tf32(float x) {
    uint32_t r;
    asm("cvt.rna.tf32.f32 %0, %1;" : "=r"(r) : "f"(x));
    return r;
}

__device__ __forceinline__ void mma_tf32(float* c, const uint32_t* a,
                                         const uint32_t* b) {
    asm volatile(
        "mma.sync.aligned.m16n8k8.row.col.f32.tf32.tf32.f32 "
        "{%0,%1,%2,%3}, {%4,%5,%6,%7}, {%8,%9}, {%0,%1,%2,%3};"
        : "+f"(c[0]), "+f"(c[1]), "+f"(c[2]), "+f"(c[3])
        : "r"(a[0]), "r"(a[1]), "r"(a[2]), "r"(a[3]), "r"(b[0]), "r"(b[1]));
}

__global__ __launch_bounds__(256, 2) void gemm_tf32_kernel(
    const float* __restrict__ A,   // [M, 256]
    const float* __restrict__ B,   // [256, 256]
    const float* __restrict__ attn_l,   // [256]
    const float* __restrict__ attn_r,   // [256]
    int M)
{
    const int K = IN_FEATS;
    const int N = HF;

    __shared__ uint32_t As[2][GBM * A_STRIDE];  // 2 x 10240 B
    __shared__ uint32_t Bs[2][GBK * B_STRIDE];  // 2 x  8704 B

    const int tid  = threadIdx.x;
    const int lane = tid & 31;
    const int warp = tid >> 5;
    const int warp_m = warp >> 2;      // 0..1 -> 64-row strip
    const int warp_n = warp & 3;       // 0..3 -> 32-col strip

    const int block_m = blockIdx.x * GBM;
    const int block_n = blockIdx.y * GBN;

    // global->smem load maps (2 float4 per thread per tile)
    const int a_row = tid >> 1;                 // 0..127
    const int a_c0  = (tid & 1) * 8;            // float col 0 or 8
    const int b_row = tid >> 4;                 // 0..15
    const int b_c0  = (tid & 15) * 8;           // float col

    const int gid = lane >> 2;                  // 0..7
    const int tig = lane & 3;                   // 0..3

    float acc[4][4][4];
#pragma unroll
    for (int mt = 0; mt < 4; mt++)
#pragma unroll
        for (int nt = 0; nt < 4; nt++)
#pragma unroll
            for (int i = 0; i < 4; i++) acc[mt][nt][i] = 0.0f;

    float4 pa0, pa1, pb0, pb1;

    // ---- load tile 0 ----
    {
        const int gm = block_m + a_row;
        if (gm < M) {
            pa0 = *reinterpret_cast<const float4*>(A + (size_t)gm * K + a_c0);
            pa1 = *reinterpret_cast<const float4*>(A + (size_t)gm * K + a_c0 + 4);
        } else {
            pa0 = make_float4(0.f, 0.f, 0.f, 0.f); pa1 = pa0;
        }
        pb0 = *reinterpret_cast<const float4*>(B + (size_t)b_row * N + block_n + b_c0);
        pb1 = *reinterpret_cast<const float4*>(B + (size_t)b_row * N + block_n + b_c0 + 4);
    }
    {
        uint32_t* as = &As[0][a_row * A_STRIDE + a_c0];
        as[0] = f2tf32(pa0.x); as[1] = f2tf32(pa0.y);
        as[2] = f2tf32(pa0.z); as[3] = f2tf32(pa0.w);
        as[4] = f2tf32(pa1.x); as[5] = f2tf32(pa1.y);
        as[6] = f2tf32(pa1.z); as[7] = f2tf32(pa1.w);
        uint32_t* bs = &Bs[0][b_row * B_STRIDE + b_c0];
        bs[0] = f2tf32(pb0.x); bs[1] = f2tf32(pb0.y);
        bs[2] = f2tf32(pb0.z); bs[3] = f2tf32(pb0.w);
        bs[4] = f2tf32(pb1.x); bs[5] = f2tf32(pb1.y);
        bs[6] = f2tf32(pb1.z); bs[7] = f2tf32(pb1.w);
    }
    __syncthreads();

    const int NT = K / GBK;   // 16 iterations
    for (int t = 0; t < NT; t++) {
        const int cur = t & 1;

        // prefetch next tile from global
        if (t < NT - 1) {
            const int k0 = (t + 1) * GBK;
            const int gm = block_m + a_row;
            if (gm < M) {
                pa0 = *reinterpret_cast<const float4*>(A + (size_t)gm * K + k0 + a_c0);
                pa1 = *reinterpret_cast<const float4*>(A + (size_t)gm * K + k0 + a_c0 + 4);
            } else {
                pa0 = make_float4(0.f, 0.f, 0.f, 0.f); pa1 = pa0;
            }
            pb0 = *reinterpret_cast<const float4*>(B + (size_t)(k0 + b_row) * N + block_n + b_c0);
            pb1 = *reinterpret_cast<const float4*>(B + (size_t)(k0 + b_row) * N + block_n + b_c0 + 4);
        }

        // compute: 2 k-chunks of 8
#pragma unroll
        for (int kc = 0; kc < 2; kc++) {
            uint32_t af[4][4], bf[4][2];
            const int kb = kc * 8;
#pragma unroll
            for (int mt = 0; mt < 4; mt++) {
                const int r0 = warp_m * 64 + mt * 16 + gid;
                af[mt][0] = As[cur][r0 * A_STRIDE + kb + tig];
                af[mt][1] = As[cur][(r0 + 8) * A_STRIDE + kb + tig];
                af[mt][2] = As[cur][r0 * A_STRIDE + kb + tig + 4];
                af[mt][3] = As[cur][(r0 + 8) * A_STRIDE + kb + tig + 4];
            }
#pragma unroll
            for (int nt = 0; nt < 4; nt++) {
                const int cn = warp_n * 32 + nt * 8 + gid;
                bf[nt][0] = Bs[cur][(kb + tig) * B_STRIDE + cn];
                bf[nt][1] = Bs[cur][(kb + tig + 4) * B_STRIDE + cn];
            }
#pragma unroll
            for (int mt = 0; mt < 4; mt++)
#pragma unroll
                for (int nt = 0; nt < 4; nt++)
                    mma_tf32(acc[mt][nt], af[mt], bf[nt]);
        }

        // store prefetched tile to other buffer
        if (t < NT - 1) {
            const int nxt = (t + 1) & 1;
            uint32_t* as = &As[nxt][a_row * A_STRIDE + a_c0];
            as[0] = f2tf32(pa0.x); as[1] = f2tf32(pa0.y);
            as[2] = f2tf32(pa0.z); as[3] = f2tf32(pa0.w);
            as[4] = f2tf32(pa1.x); as[5] = f2tf32(pa1.y);
            as[6] = f2tf32(pa1.z); as[7] = f2tf32(pa1.w);
            uint32_t* bs = &Bs[nxt][b_row * B_STRIDE + b_c0];
            bs[0] = f2tf32(pb0.x); bs[1] = f2tf32(pb0.y);
            bs[2] = f2tf32(pb0.z); bs[3] = f2tf32(pb0.w);
            bs[4] = f2tf32(pb1.x); bs[5] = f2tf32(pb1.y);
            bs[6] = f2tf32(pb1.z); bs[7] = f2tf32(pb1.w);
            __syncthreads();
        }
    }

    // ---- epilogue 1: write h ----
#pragma unroll
    for (int mt = 0; mt < 4; mt++) {
        const int r0 = block_m + warp_m * 64 + mt * 16 + gid;
        const int r1 = r0 + 8;
#pragma unroll
        for (int nt = 0; nt < 4; nt++) {
            const int cn = block_n + warp_n * 32 + nt * 8 + tig * 2;
            if (r0 < M) {
                float2 v = make_float2(acc[mt][nt][0], acc[mt][nt][1]);
                *reinterpret_cast<float2*>(g_h + (size_t)r0 * HF + cn) = v;
            }
            if (r1 < M) {
                float2 v = make_float2(acc[mt][nt][2], acc[mt][nt][3]);
                *reinterpret_cast<float2*>(g_h + (size_t)r1 * HF + cn) = v;
            }
        }
    }

    // ---- epilogue 2: fused attn partial dot products ----
    // This warp's 32-col strip is entirely within one head (32 | 64).
    {
        const int head = (block_n + warp_n * 32) >> 6;
        float al[8], ar[8];
#pragma unroll
        for (int nt = 0; nt < 4; nt++) {
            const int c = block_n + warp_n * 32 + nt * 8 + tig * 2;
            al[nt * 2]     = attn_l[c];
            al[nt * 2 + 1] = attn_l[c + 1];
            ar[nt * 2]     = attn_r[c];
            ar[nt * 2 + 1] = attn_r[c + 1];
        }
#pragma unroll
        for (int mt = 0; mt < 4; mt++) {
            float pl0 = 0.f, pr0 = 0.f, pl1 = 0.f, pr1 = 0.f;
#pragma unroll
            for (int nt = 0; nt < 4; nt++) {
                pl0 = fmaf(acc[mt][nt][0], al[nt*2],   pl0);
                pl0 = fmaf(acc[mt][nt][1], al[nt*2+1], pl0);
                pr0 = fmaf(acc[mt][nt][0], ar[nt*2],   pr0);
                pr0 = fmaf(acc[mt][nt][1], ar[nt*2+1], pr0);
                pl1 = fmaf(acc[mt][nt][2], al[nt*2],   pl1);
                pl1 = fmaf(acc[mt][nt][3], al[nt*2+1], pl1);
                pr1 = fmaf(acc[mt][nt][2], ar[nt*2],   pr1);
                pr1 = fmaf(acc[mt][nt][3], ar[nt*2+1], pr1);
            }
            // reduce over the 4 tig lanes (stride-1 lane groups)
#pragma unroll
            for (int off = 1; off <= 2; off <<= 1) {
                pl0 += __shfl_xor_sync(0xFFFFFFFFu, pl0, off);
                pr0 += __shfl_xor_sync(0xFFFFFFFFu, pr0, off);
                pl1 += __shfl_xor_sync(0xFFFFFFFFu, pl1, off);
                pr1 += __shfl_xor_sync(0xFFFFFFFFu, pr1, off);
            }
            if (tig == 0) {
                const int r0 = block_m + warp_m * 64 + mt * 16 + gid;
                const int r1 = r0 + 8;
                if (r0 < M) {
                    atomicAdd(&g_attn_row[(size_t)r0 * NHEADS + head], pl0);
                    atomicAdd(&g_attn_col[(size_t)r0 * NHEADS + head], pr0);
                }
                if (r1 < M) {
                    atomicAdd(&g_attn_row[(size_t)r1 * NHEADS + head], pl1);
                    atomicAdd(&g_attn_col[(size_t)r1 * NHEADS + head], pr1);
                }
            }
        }
    }
}

// ---------------------------------------------------------------------------
// Kernel 2: softmax + weighted gather-aggregate.
// ONE WARP per destination (8 dst/CTA): all phases warp-synchronous, no CTA
// barriers. Each lane owns 8 output floats -> 2 float4 gathers per edge
// (32 independent LDG.128 per lane in the deg==16 fast path).
// ---------------------------------------------------------------------------
__global__ __launch_bounds__(256) void gat_agg_kernel(float* __restrict__ out,
                                                      int n)
{
    const int tid  = threadIdx.x;
    const int wid  = tid >> 5;          // 0..7
    const int lane = tid & 31;
    const int dst  = blockIdx.x * 8 + wid;
    if (dst >= n) return;

    __shared__ int   s_src[8][MAXDEG];
    __shared__ float s_alpha[8][MAXDEG * NHEADS];

    const int e0 = g_row_ptr[dst];
    int deg = g_row_ptr[dst + 1] - e0;
    if (deg > MAXDEG) deg = MAXDEG;

    if (lane < deg) s_src[wid][lane] = g_col_ind[e0 + lane];
    __syncwarp();

    // raw scores + leaky relu: 64 (edge, head) pairs, 2 per lane
#pragma unroll
    for (int p = lane; p < MAXDEG * NHEADS; p += 32) {
        if (p < deg * NHEADS) {
            const int e  = p >> 2;
            const int hh = p & 3;
            float s = g_attn_row[(size_t)dst * NHEADS + hh] +
                      g_attn_col[(size_t)s_src[wid][e] * NHEADS + hh];
            s_alpha[wid][p] = (s >= 0.f) ? s : NEG_SLOPE * s;
        }
    }
    __syncwarp();

    // per-head softmax over deg edges (lanes 0..3)
    if (lane < NHEADS) {
        float m = -1e30f;
        for (int e = 0; e < deg; e++)
            m = fmaxf(m, s_alpha[wid][e * NHEADS + lane]);
        float sum = 0.f;
        for (int e = 0; e < deg; e++) {
            float ex = __expf(s_alpha[wid][e * NHEADS + lane] - m);
            s_alpha[wid][e * NHEADS + lane] = ex;
            sum += ex;
        }
        const float inv = 1.0f / sum;
        for (int e = 0; e < deg; e++)
            s_alpha[wid][e * NHEADS + lane] *= inv;
    }
    __syncwarp();

    // aggregate: lane owns 8 consecutive output floats (all in one head)
    const int h = lane >> 3;            // head = (lane*8)/64
    const int foff = lane * 8;
    float4 acc0 = make_float4(0.f, 0.f, 0.f, 0.f);
    float4 acc1 = make_float4(0.f, 0.f, 0.f, 0.f);

    if (deg == MAXDEG) {
#pragma unroll
        for (int e = 0; e < MAXDEG; e++) {
            const float a = s_alpha[wid][e * NHEADS + h];
            const float* row = g_h + (size_t)s_src[wid][e] * HF + foff;
            const float4 v0 = *reinterpret_cast<const float4*>(row);
            const float4 v1 = *reinterpret_cast<const float4*>(row + 4);
            acc0.x = fmaf(a, v0.x, acc0.x); acc0.y = fmaf(a, v0.y, acc0.y);
            acc0.z = fmaf(a, v0.z, acc0.z); acc0.w = fmaf(a, v0.w, acc0.w);
            acc1.x = fmaf(a, v1.x, acc1.x); acc1.y = fmaf(a, v1.y, acc1.y);
            acc1.z = fmaf(a, v1.z, acc1.z); acc1.w = fmaf(a, v1.w, acc1.w);
        }
    } else {
        for (int e = 0; e < deg; e++) {
            const float a = s_alpha[wid][e * NHEADS + h];
            const float* row = g_h + (size_t)s_src[wid][e] * HF + foff;
            const float4 v0 = *reinterpret_cast<const float4*>(row);
            const float4 v1 = *reinterpret_cast<const float4*>(row + 4);
            acc0.x = fmaf(a, v0.x, acc0.x); acc0.y = fmaf(a, v0.y, acc0.y);
            acc0.z = fmaf(a, v0.z, acc0.z); acc0.w = fmaf(a, v0.w, acc0.w);
            acc1.x = fmaf(a, v1.x, acc1.x); acc1.y = fmaf(a, v1.y, acc1.y);
            acc1.z = fmaf(a, v1.z, acc1.z); acc1.w = fmaf(a, v1.w, acc1.w);
        }
    }
    float* orow = out + (size_t)dst * HF + foff;
    *reinterpret_cast<float4*>(orow)     = acc0;
    *reinterpret_cast<float4*>(orow + 4) = acc1;
}

// ---------------------------------------------------------------------------
// Launch
// Inputs (metadata order): row_ptr(N+1), col_ind(E), col_ptr(N+1), row_ind(E),
// feat(f32,N*256), W(f32,256*256), attn_l(f32,256), attn_r(f32,256)
// Output: f32 [N, 4, 64]
// ---------------------------------------------------------------------------
extern "C" void kernel_launch(void* const* d_in, const int* in_sizes, int n_in,
                              void* d_out, int out_size)
{
    const void*  row_ptr_raw = d_in[0];
    const void*  col_ind_raw = d_in[1];
    const float* feat   = (const float*)d_in[4];
    const float* W      = (const float*)d_in[5];
    const float* attn_l = (const float*)d_in[6];
    const float* attn_r = (const float*)d_in[7];
    float* out = (float*)d_out;

    const int n_plus1 = in_sizes[0];      // N + 1
    const int n = n_plus1 - 1;            // 50000
    int e = in_sizes[1];                  // 800000
    if (e > EMAX) e = EMAX;

    // 0) normalize indices to int32 + zero attn accumulators
    {
        const int nh = n * NHEADS;
        int total = (e > n_plus1) ? e : n_plus1;
        if (nh > total) total = nh;
        convert_idx_kernel<<<(total + 255) / 256, 256>>>(
            row_ptr_raw, col_ind_raw, n_plus1, e, nh);
    }

    // 1) h = feat @ W (tf32 tensor cores) + fused attn partial dots
    dim3 ggrid((n + GBM - 1) / GBM, HF / GBN);
    gemm_tf32_kernel<<<ggrid, 256>>>(feat, W, attn_l, attn_r, n);

    // 2) softmax + aggregate
    gat_agg_kernel<<<(n + 7) / 8, 256>>>(out, n);
}